// round 9
// baseline (speedup 1.0000x reference)
#include <cuda_runtime.h>
#include <math.h>
#include <stdint.h>

#define BATCH 512
#define HID   512
#define NCLS  1000
#define MC    4000
#define INV_SIGMA (1.0f/10.0f)

#if defined(__CUDA_ARCH__) && (__CUDA_ARCH__ == 1030) && defined(__CUDA_ARCH_FEAT_SM103_ALL)
#define HAS_TC 1
#else
#define HAS_TC 0
#endif

// ---------------- scratch ----------------
__device__ __align__(16) float g_a[4096];        // ||w_m||^2 (exact fp32)
__device__ __align__(16) float g_fsq[BATCH];     // ||f_b||^2
__device__ __align__(16) float g_s[HID];         // col sums of W (from rounded Wt)
__device__ __align__(16) float g_u[HID];         // u_k = sum_m a_m Wt[k,m]
__device__ __align__(16) float g_Wt[512*4096];   // W^T, tf32-RN-rounded, stride 4096
// Gram partials: 10 (ti<=tj) tiles x 5 m-chunks x 128x128
__device__ __align__(16) float g_G2[10*5*16384];
__device__ double g_f2p[20];                     // F2 partials per block

__constant__ int c_ti[10] = {0,0,0,0,1,1,1,2,2,3};
__constant__ int c_tj[10] = {0,1,2,3,1,2,3,2,3,3};

// ---------------- PTX helpers ----------------
__device__ __forceinline__ uint32_t smem_u32(const void* p) {
    uint32_t a;
    asm("{ .reg .u64 t; cvta.to.shared.u64 t, %1; cvt.u32.u64 %0, t; }"
        : "=r"(a) : "l"(p));
    return a;
}
__device__ __forceinline__ uint32_t elect_one() {
    uint32_t pred;
    asm volatile("{\n\t.reg .pred p;\n\telect.sync _|p, 0xFFFFFFFF;\n\t"
                 "selp.b32 %0, 1, 0, p;\n\t}" : "=r"(pred));
    return pred;
}
__device__ __forceinline__ float tf32_rn(float x) {
    float r;
    asm("cvt.rna.tf32.f32 %0, %1;" : "=f"(r) : "f"(x));
    return r;
}
#define MBAR_INIT(addr, cnt) \
    asm volatile("mbarrier.init.shared.b64 [%0], %1;" :: "r"(addr), "r"(cnt) : "memory")
#define MBAR_WAIT(addr, par) do { \
    uint32_t _m = (addr), _p = (par), _d; \
    asm volatile("{\n\t.reg .pred p;\n\t" \
        "mbarrier.try_wait.parity.acquire.cta.shared::cta.b64 p, [%1], %2;\n\t" \
        "selp.b32 %0, 1, 0, p;\n\t}" : "=r"(_d) : "r"(_m), "r"(_p) : "memory"); \
    if (!_d) { \
        asm volatile("{\n\t.reg .pred P1;\n\tWL%=:\n\t" \
            "mbarrier.try_wait.parity.acquire.cta.shared::cta.b64 P1, [%0], %1, 0x989680;\n\t" \
            "@P1 bra.uni WD%=;\n\tbra.uni WL%=;\n\tWD%=:\n\t}" \
            :: "r"(_m), "r"(_p) : "memory"); \
    } } while (0)

#if HAS_TC
#define TC_ALLOC(smem_addr, n) \
    asm volatile("tcgen05.alloc.cta_group::1.sync.aligned.shared::cta.b32 [%0], %1;" \
        :: "r"(smem_addr), "r"(n) : "memory")
#define TC_DEALLOC(tmem, n) \
    asm volatile("tcgen05.dealloc.cta_group::1.sync.aligned.b32 %0, %1;" :: "r"(tmem), "r"(n))
#define TC_RELINQ() \
    asm volatile("tcgen05.relinquish_alloc_permit.cta_group::1.sync.aligned;")
#define TC_COMMIT(mbar) \
    asm volatile("tcgen05.commit.cta_group::1.mbarrier::arrive::one.shared::cluster.b64 [%0];" \
        :: "r"(mbar) : "memory")
#define TC_FENCE_AFTER() asm volatile("tcgen05.fence::after_thread_sync;" ::: "memory")
#define TC_FENCE_BEFORE() asm volatile("tcgen05.fence::before_thread_sync;" ::: "memory")
#define TC_WAIT_LD() asm volatile("tcgen05.wait::ld.sync.aligned;" ::: "memory")
#define LDTM_X32(r, addr) \
    asm volatile("tcgen05.ld.sync.aligned.32x32b.x32.b32 " \
        "{%0,%1,%2,%3,%4,%5,%6,%7,%8,%9,%10,%11,%12,%13,%14,%15," \
        "%16,%17,%18,%19,%20,%21,%22,%23,%24,%25,%26,%27,%28,%29,%30,%31}, [%32];" \
        : "=r"((r)[0]),"=r"((r)[1]),"=r"((r)[2]),"=r"((r)[3]), \
          "=r"((r)[4]),"=r"((r)[5]),"=r"((r)[6]),"=r"((r)[7]), \
          "=r"((r)[8]),"=r"((r)[9]),"=r"((r)[10]),"=r"((r)[11]), \
          "=r"((r)[12]),"=r"((r)[13]),"=r"((r)[14]),"=r"((r)[15]), \
          "=r"((r)[16]),"=r"((r)[17]),"=r"((r)[18]),"=r"((r)[19]), \
          "=r"((r)[20]),"=r"((r)[21]),"=r"((r)[22]),"=r"((r)[23]), \
          "=r"((r)[24]),"=r"((r)[25]),"=r"((r)[26]),"=r"((r)[27]), \
          "=r"((r)[28]),"=r"((r)[29]),"=r"((r)[30]),"=r"((r)[31]) \
        : "r"(addr))

// SW128 K-major desc: LBO=1, SBO=64, version=1, layout=2
static __device__ __forceinline__ uint64_t make_desc(uint32_t addr) {
    const uint64_t base = (uint64_t(2) << 61) | (uint64_t(1) << 46)
                        | (uint64_t(64) << 32) | (uint64_t(1) << 16);
    return base | ((uint64_t)(addr >> 4) & 0x3FFF);
}
// tf32 SS MMA, cg1: D[128,128] += A[128,8] * B[128,8]^T
__device__ __forceinline__ void mma_tf32(uint32_t d, uint64_t ad, uint64_t bd,
                                         uint32_t idesc, uint32_t en) {
    asm volatile("{\n\t.reg .pred p;\n\tsetp.ne.u32 p, %5, 0;\n\t"
        "tcgen05.mma.cta_group::1.kind::tf32 [%0], %1, %2, %3, {%4,%4,%4,%4}, p;\n\t}"
        :: "r"(d), "l"(ad), "l"(bd), "r"(idesc), "r"(0u), "r"(en) : "memory");
}
#endif  // HAS_TC

__device__ __forceinline__ uint32_t swz(uint32_t o) { return o ^ ((o >> 3) & 0x70); }

__device__ __forceinline__ void cp16(uint32_t dst, const void* src, bool valid) {
    int sz = valid ? 16 : 0;
    asm volatile("cp.async.cg.shared.global [%0], [%1], 16, %2;"
                 :: "r"(dst), "l"(src), "r"(sz));
}

// ---------------- pipeline layout (shared by both tcgen05 GEMMs) ----------------
#define STG       4
#define STG_BYTES 16384     // 128 rows x 128B
#define OFF_A     1024
#define OFF_B     (1024 + STG*STG_BYTES)
#define SMEM_TC   (1024 + 2*STG*STG_BYTES)
// idesc: cF32 | aTF32 | bTF32 | N=128 | M=128
#define IDESC_TF32 ((1u<<4) | (2u<<7) | (2u<<10) | (16u<<17) | (8u<<24))

// ================= STAGE 1: transpose (blocks 0..1999) || pre (2000..2140) ======
// 256 threads per block.
__global__ void __launch_bounds__(256) k_stage1(const float* __restrict__ W,
                                                const float* __restrict__ F) {
    __shared__ float tile[32][33];
    int tid = threadIdx.x;
    if (blockIdx.x < 2000) {
        // transpose + tf32-RN round: Wt[k][m] = rn(W[m][k])
        int k0 = (blockIdx.x & 15) * 32, m0 = (blockIdx.x >> 4) * 32;
        int x = tid & 31, y = tid >> 5;         // y in 0..7
        #pragma unroll
        for (int i = 0; i < 4; i++)
            tile[y + i * 8][x] = W[(size_t)(m0 + y + i * 8) * HID + k0 + x];
        __syncthreads();
        #pragma unroll
        for (int i = 0; i < 4; i++)
            g_Wt[(size_t)(k0 + y + i * 8) * 4096 + m0 + x] = tf32_rn(tile[x][y + i * 8]);
    } else {
        // pre: a_m = ||w_m||^2 (4 rows/warp, all loads up-front for MLP=16); fsq
        int warp = ((blockIdx.x - 2000) * 256 + tid) >> 5;   // 0..1127
        int lane = tid & 31;
        int r0 = warp * 4;
        bool isW = (r0 < MC);                   // 4000 % 4 == 0: no straddle
        const float* base = isW ? W : F;
        int rb = isW ? r0 : (r0 - MC);
        float4 v[4][4];
        #pragma unroll
        for (int j = 0; j < 4; j++)
            #pragma unroll
            for (int q = 0; q < 4; q++)
                v[j][q] = reinterpret_cast<const float4*>(
                    base + (size_t)(rb + j) * HID)[lane + q * 32];
        float acc[4];
        #pragma unroll
        for (int j = 0; j < 4; j++) {
            float a = 0.f;
            #pragma unroll
            for (int q = 0; q < 4; q++)
                a += v[j][q].x*v[j][q].x + v[j][q].y*v[j][q].y
                   + v[j][q].z*v[j][q].z + v[j][q].w*v[j][q].w;
            acc[j] = a;
        }
        #pragma unroll
        for (int o = 16; o > 0; o >>= 1)
            #pragma unroll
            for (int j = 0; j < 4; j++)
                acc[j] += __shfl_down_sync(0xffffffffu, acc[j], o);
        if (lane == 0) {
            #pragma unroll
            for (int j = 0; j < 4; j++) {
                if (isW) g_a[r0 + j] = acc[j];
                else     g_fsq[rb + j] = acc[j];
            }
        }
    }
}

// ================= STAGE 2: gram (blocks 0..49) || su (50..113) =================
// 128 threads per block, SMEM_TC dynamic smem.
#define GK_NCHUNK 25

#if HAS_TC
__device__ __forceinline__ void gram_load_chunk(uint32_t sb, int stage, int c,
                                                int K0, int L0, int mbase, int tid) {
    int moff = mbase + c * 32;
    uint32_t dA = sb + OFF_A + stage * STG_BYTES;
    uint32_t dB = sb + OFF_B + stage * STG_BYTES;
    #pragma unroll
    for (int p = 0; p < 8; p++) {
        int idx = p * 128 + tid;
        int r = idx >> 3, seg = idx & 7;
        uint32_t off = swz((uint32_t)(r * 128 + seg * 16));
        cp16(dA + off, g_Wt + (size_t)(K0 + r) * 4096 + moff + seg * 4, true);
        cp16(dB + off, g_Wt + (size_t)(L0 + r) * 4096 + moff + seg * 4, true);
    }
}
#endif

__global__ void __launch_bounds__(128, 1) k_stage2() {
    int tid = threadIdx.x, wid = tid >> 5, lane = tid & 31;
    if (blockIdx.x >= 50) {
        // ---- su: s_k, u_k ; 64 blocks x 4 warps x 2 k ----
        int kb = (int)(blockIdx.x - 50) * 8 + wid * 2;
        #pragma unroll
        for (int j = 0; j < 2; j++) {
            int k = kb + j;
            const float4* row = reinterpret_cast<const float4*>(g_Wt + (size_t)k * 4096);
            const float4* av  = reinterpret_cast<const float4*>(g_a);
            float s = 0.f, u = 0.f;
            #pragma unroll 8
            for (int q = 0; q < 32; q++) {
                int i4 = lane + q * 32;
                if (i4 < 1000) {
                    float4 w = row[i4];
                    float4 a = av[i4];
                    s += w.x + w.y + w.z + w.w;
                    u += a.x*w.x + a.y*w.y + a.z*w.z + a.w*w.w;
                }
            }
            #pragma unroll
            for (int o = 16; o > 0; o >>= 1) {
                s += __shfl_down_sync(0xffffffffu, s, o);
                u += __shfl_down_sync(0xffffffffu, u, o);
            }
            if (lane == 0) { g_s[k] = s; g_u[k] = u; }
        }
        return;
    }
    // ---- gram: G = Wt . Wt^T, tile t, m-chunk z ----
#if HAS_TC
    extern __shared__ char smem[];
    uint32_t sb = smem_u32(smem);
    int t = blockIdx.x / 5, z = blockIdx.x % 5;
    int K0 = c_ti[t] * 128, L0 = c_tj[t] * 128, mbase = z * 800;

    if (tid < 4) MBAR_INIT(sb + tid * 8, 1);
    if (wid == 0) { TC_ALLOC(sb + 32, 128); TC_RELINQ(); }
    __syncthreads();
    uint32_t tmem;
    asm volatile("ld.shared.b32 %0, [%1];" : "=r"(tmem) : "r"(sb + 32));

    #pragma unroll
    for (int c0 = 0; c0 < 3; c0++) {
        gram_load_chunk(sb, c0, c0, K0, L0, mbase, tid);
        asm volatile("cp.async.commit_group;" ::: "memory");
    }

    uint32_t phv = 0;
    for (int c = 0; c < GK_NCHUNK; c++) {
        int s = c & 3;
        if (c + 3 < GK_NCHUNK) {
            int so = (c + 3) & 3;
            if (c >= 1) {
                MBAR_WAIT(sb + so * 8, (phv >> so) & 1u);
                phv ^= (1u << so);
            }
            gram_load_chunk(sb, so, c + 3, K0, L0, mbase, tid);
        }
        asm volatile("cp.async.commit_group;" ::: "memory");
        asm volatile("cp.async.wait_group 3;" ::: "memory");
        __syncthreads();
        if (wid == 0 && elect_one()) {
            asm volatile("fence.proxy.async.shared::cta;" ::: "memory");
            uint64_t ad = make_desc(sb + OFF_A + s * STG_BYTES);
            uint64_t bd = make_desc(sb + OFF_B + s * STG_BYTES);
            #pragma unroll
            for (int k = 0; k < 4; k++)
                mma_tf32(tmem, ad + k * 2, bd + k * 2, IDESC_TF32,
                         (c > 0 || k > 0) ? 1u : 0u);
            TC_COMMIT(sb + s * 8);
        }
    }
    __syncthreads();
    {
        int so = (GK_NCHUNK - 1) & 3;
        MBAR_WAIT(sb + so * 8, (phv >> so) & 1u);
    }
    TC_FENCE_AFTER();

    float* dst = g_G2 + ((size_t)blockIdx.x << 14);
    int row = wid * 32 + lane;
    #pragma unroll
    for (int j0 = 0; j0 < 128; j0 += 32) {
        uint32_t r[32];
        LDTM_X32(r, tmem + j0);
        TC_WAIT_LD();
        #pragma unroll
        for (int j4 = 0; j4 < 8; j4++) {
            float4 v = make_float4(__uint_as_float(r[j4*4+0]), __uint_as_float(r[j4*4+1]),
                                   __uint_as_float(r[j4*4+2]), __uint_as_float(r[j4*4+3]));
            *reinterpret_cast<float4*>(&dst[(size_t)row * 128 + j0 + j4 * 4]) = v;
        }
    }
    TC_FENCE_BEFORE();
    __syncthreads();
    if (wid == 0) TC_DEALLOC(tmem, 128);
#else
    // correct fallback (never selected on GB300)
    int t = blockIdx.x / 5, z = blockIdx.x % 5;
    int K0 = c_ti[t] * 128, L0 = c_tj[t] * 128, mbase = z * 800;
    float* dst = g_G2 + ((size_t)blockIdx.x << 14);
    for (int e = tid; e < 16384; e += blockDim.x) {
        int k = K0 + (e >> 7), l = L0 + (e & 127);
        float acc = 0.f;
        for (int m = 0; m < 800; m++)
            acc = fmaf(g_Wt[(size_t)k * 4096 + mbase + m],
                       g_Wt[(size_t)l * 4096 + mbase + m], acc);
        dst[e] = acc;
    }
#endif
}

// ================= STAGE 3: fw (blocks 0..127) || f2 (128..147) =================
#define KC      32
#define NCHUNK  16

#if HAS_TC
__device__ __forceinline__ void fw_load_chunk(uint32_t sb, int stage, int c,
                                              const float* __restrict__ W,
                                              const float* __restrict__ F,
                                              int m0, int b0, int tid) {
    int kc = c * KC;
    uint32_t dA = sb + OFF_A + stage * STG_BYTES;
    uint32_t dB = sb + OFF_B + stage * STG_BYTES;
    #pragma unroll
    for (int p = 0; p < 8; p++) {
        int idx = p * 128 + tid;
        int r = idx >> 3, seg = idx & 7;
        uint32_t off = swz((uint32_t)(r * 128 + seg * 16));
        int m = m0 + r;
        bool v = (m < MC);
        cp16(dA + off, W + (size_t)(v ? m : 0) * HID + kc + seg * 4, v);
        cp16(dB + off, F + (size_t)(b0 + r) * HID + kc + seg * 4, true);
    }
}
#endif

__global__ void __launch_bounds__(128, 1) k_stage3(const float* __restrict__ F,
                                                   const float* __restrict__ W,
                                                   float* __restrict__ out) {
    int tid = threadIdx.x, wid = tid >> 5, lane = tid & 31;
    if (blockIdx.x >= 128) {
        // ---- f2: 20 blocks, grid-stride over 10*16384 elems ----
        double acc = 0.0;
        int start = (int)(blockIdx.x - 128) * 128 + tid;
        for (int i = start; i < 10 * 16384; i += 20 * 128) {
            int t = i >> 14, e = i & 16383;
            float g = 0.f;
            #pragma unroll
            for (int z = 0; z < 5; z++) g += g_G2[((size_t)(t * 5 + z) << 14) + e];
            double w = (c_ti[t] == c_tj[t]) ? 1.0 : 2.0;
            acc += w * (double)g * (double)g;
        }
        __shared__ double sd[128];
        sd[tid] = acc;
        __syncthreads();
        for (int o = 64; o > 0; o >>= 1) {
            if (tid < o) sd[tid] += sd[tid + o];
            __syncthreads();
        }
        if (tid == 0) g_f2p[blockIdx.x - 128] = sd[0];
        return;
    }
    // ---- fw: tcgen05 GEMM + fused distance epilogue ----
#if HAS_TC
    extern __shared__ char smem[];
    uint32_t sb = smem_u32(smem);
    int m0 = (int)(blockIdx.x & 31) * 128, b0 = (int)(blockIdx.x >> 5) * 128;

    if (tid < 4) MBAR_INIT(sb + tid * 8, 1);
    if (wid == 0) { TC_ALLOC(sb + 32, 128); TC_RELINQ(); }
    __syncthreads();
    uint32_t tmem;
    asm volatile("ld.shared.b32 %0, [%1];" : "=r"(tmem) : "r"(sb + 32));

    #pragma unroll
    for (int c0 = 0; c0 < 3; c0++) {
        fw_load_chunk(sb, c0, c0, W, F, m0, b0, tid);
        asm volatile("cp.async.commit_group;" ::: "memory");
    }

    uint32_t phv = 0;
    for (int c = 0; c < NCHUNK; c++) {
        int s = c & 3;
        if (c + 3 < NCHUNK) {
            int so = (c + 3) & 3;
            if (c >= 1) {
                MBAR_WAIT(sb + so * 8, (phv >> so) & 1u);
                phv ^= (1u << so);
            }
            fw_load_chunk(sb, so, c + 3, W, F, m0, b0, tid);
        }
        asm volatile("cp.async.commit_group;" ::: "memory");
        asm volatile("cp.async.wait_group 3;" ::: "memory");
        __syncthreads();
        if (wid == 0 && elect_one()) {
            asm volatile("fence.proxy.async.shared::cta;" ::: "memory");
            uint64_t ad = make_desc(sb + OFF_A + s * STG_BYTES);
            uint64_t bd = make_desc(sb + OFF_B + s * STG_BYTES);
            #pragma unroll
            for (int k = 0; k < 4; k++)
                mma_tf32(tmem, ad + k * 2, bd + k * 2, IDESC_TF32,
                         (c > 0 || k > 0) ? 1u : 0u);
            TC_COMMIT(sb + s * 8);
        }
    }
    __syncthreads();
    MBAR_WAIT(sb + 3 * 8, (phv >> 3) & 1u);
    TC_FENCE_AFTER();

    // epilogue: x = a_m - 2*fw ; min over 4-lane quads ; exp
    int m = m0 + wid * 32 + lane;
    float a = (m < MC) ? __ldg(&g_a[m]) : __int_as_float(0x7f800000);
    int grp = m >> 2;
    #pragma unroll
    for (int j0 = 0; j0 < 128; j0 += 32) {
        uint32_t r[32];
        LDTM_X32(r, tmem + j0);
        TC_WAIT_LD();
        #pragma unroll
        for (int jj = 0; jj < 32; jj++) {
            float fw = __uint_as_float(r[jj]);
            float x = fmaf(-2.f, fw, a);
            x = fminf(x, __shfl_xor_sync(0xffffffffu, x, 1));
            x = fminf(x, __shfl_xor_sync(0xffffffffu, x, 2));
            if ((lane & 3) == 0 && m < MC) {
                int b = b0 + j0 + jj;
                out[(size_t)b * (NCLS + 1) + grp] =
                    expf(-(__ldg(&g_fsq[b]) + x) * INV_SIGMA);
            }
        }
    }
    TC_FENCE_BEFORE();
    __syncthreads();
    if (wid == 0) TC_DEALLOC(tmem, 128);
#else
    // correct fallback (never selected on GB300)
    int m0 = (int)(blockIdx.x & 31) * 128, b0 = (int)(blockIdx.x >> 5) * 128;
    int m = m0 + tid;
    if (m >= MC) return;
    float a = g_a[m];
    int grp = m >> 2;
    const float* wrow = W + (size_t)m * HID;
    for (int jb = 0; jb < 128; jb++) {
        int b = b0 + jb;
        const float* frow = F + (size_t)b * HID;
        float dot = 0.f;
        for (int k = 0; k < HID; k++) dot = fmaf(wrow[k], frow[k], dot);
        float x = fmaf(-2.f, dot, a);
        x = fminf(x, __shfl_xor_sync(0xffffffffu, x, 1));
        x = fminf(x, __shfl_xor_sync(0xffffffffu, x, 2));
        if ((tid & 3) == 0)
            out[(size_t)b * (NCLS + 1) + grp] =
                expf(-(g_fsq[b] + x) * INV_SIGMA);
    }
#endif
}

// ---------------- finalize: fp64 scalar reductions + rw column ----------------
__global__ void k_finalize(float* __restrict__ out) {
    __shared__ double sd[512], sd2[512];
    __shared__ float rw_s;
    int t = threadIdx.x;

    double la = 0.0, la2 = 0.0;
    #pragma unroll
    for (int i = 0; i < 8; i++) {
        int idx = t * 8 + i;
        if (idx < MC) {
            double a = (double)g_a[idx];
            la += a; la2 += a * a;
        }
    }
    double ls2 = (double)g_s[t] * (double)g_s[t];
    double lat = (double)g_u[t] * (double)g_s[t];
    double lf2 = (t < 20) ? g_f2p[t] : 0.0;

    double tot[5];
    // pass 1: (la, la2)
    sd[t] = la; sd2[t] = la2;
    __syncthreads();
    for (int o = 256; o > 0; o >>= 1) {
        if (t < o) { sd[t] += sd[t + o]; sd2[t] += sd2[t + o]; }
        __syncthreads();
    }
    tot[0] = sd[0]; tot[1] = sd2[0];
    __syncthreads();
    // pass 2: (ls2, lat)
    sd[t] = ls2; sd2[t] = lat;
    __syncthreads();
    for (int o = 256; o > 0; o >>= 1) {
        if (t < o) { sd[t] += sd[t + o]; sd2[t] += sd2[t + o]; }
        __syncthreads();
    }
    tot[2] = sd[0]; tot[3] = sd2[0];
    __syncthreads();
    // pass 3: f2
    sd[t] = lf2;
    __syncthreads();
    for (int o = 256; o > 0; o >>= 1) {
        if (t < o) sd[t] += sd[t + o];
        __syncthreads();
    }
    tot[4] = sd[0];

    if (t == 0) {
        double sum_a = tot[0], sum_a2 = tot[1], s2 = tot[2], sum_at = tot[3], F2 = tot[4];
        double mc = (double)MC;
        double denom = 2.0 / (mc * mc - mc);
        double S1 = mc * sum_a - s2;
        double mu = denom * S1;
        double S2 = mc * sum_a2 + sum_a * sum_a + 2.0 * F2 - 4.0 * sum_at;
        rw_s = (float)(denom * S2 - mu * mu);
    }
    __syncthreads();
    out[(size_t)t * (NCLS + 1) + NCLS] = rw_s;
}

extern "C" void kernel_launch(void* const* d_in, const int* in_sizes, int n_in,
                              void* d_out, int out_size) {
    const float* F = (const float*)d_in[0];   // [512,512]
    const float* W = (const float*)d_in[1];   // [4000,512]
    float* out = (float*)d_out;               // [512,1001]
    (void)in_sizes; (void)n_in; (void)out_size;

    static bool inited = false;
    if (!inited) {
        cudaFuncSetAttribute(k_stage2, cudaFuncAttributeMaxDynamicSharedMemorySize,
                             SMEM_TC);
        cudaFuncSetAttribute(k_stage3, cudaFuncAttributeMaxDynamicSharedMemorySize,
                             SMEM_TC);
        inited = true;
    }

    k_stage1<<<2141, 256>>>(W, F);              // transpose || pre
    k_stage2<<<114, 128, SMEM_TC>>>();          // gram || su
    k_stage3<<<148, 128, SMEM_TC>>>(F, W, out); // fw || f2  (exactly one wave)
    k_finalize<<<1, 512>>>(out);
}